// round 12
// baseline (speedup 1.0000x reference)
#include <cuda_runtime.h>
#include <cuda_fp16.h>
#include <math.h>
#include <stdint.h>

#define F_IN   4096
#define F_OUT  2048
#define BATCH  2048
#define N_ITER 10
#define SECURE_MIN 1e-5f
#define EPS_NORM   1e-20f

// static power-of-2 operand scales (exact; cancelled analytically)
#define S_W   65536.0f   // Wn, WnT
#define S_H   4096.0f    // ht
#define S_R   256.0f     // ratio
#define S_REC 4096.0f    // recon half storage
#define S_X   4096.0f    // xn half storage
#define ESC1 (1.0f / (S_H * S_W))
#define ESC2 (1.0f / (S_R * S_W))

// ---------------- GEMM tiling (proven config) ----------------
#define BM 128
#define BN 128
#define BK 64
#define STAGES 3
#define TILE_BYTES (BM * 128)
#define STAGE_BYTES (2 * TILE_BYTES)
#define SMEM_TOTAL (STAGES * STAGE_BYTES)  // 96 KB -> 2 CTA/SM

// ---------------- scratch ----------------
__device__ __align__(1024) __half g_Wn_h  [(size_t)F_OUT * F_IN];
__device__ __align__(1024) __half g_WnT_h [(size_t)F_IN  * F_OUT];
__device__ __align__(1024) __half g_rat_h [(size_t)BATCH * F_IN];
__device__ __align__(1024) __half g_ht_h  [(size_t)BATCH * F_OUT];
__device__ __align__(1024) __half g_xn_h  [(size_t)BATCH * F_IN];
__device__ __align__(1024) __half g_rec_h [(size_t)BATCH * F_IN];
__device__ float g_rec0[F_IN];      // S_W * colsum(Wn), accumulated by transpose
__device__ float g_rowsum[BATCH];   // per-row sum of clipped recon (true units)

// ---------------- PTX helpers ----------------
__device__ __forceinline__ uint32_t smem_u32(const void* p) {
    uint32_t a;
    asm("{ .reg .u64 t; cvta.to.shared.u64 t, %1; cvt.u32.u64 %0, t; }"
        : "=r"(a) : "l"(p));
    return a;
}
__device__ __forceinline__ void cp_async16(uint32_t dst, const void* src) {
    asm volatile("cp.async.cg.shared.global [%0], [%1], 16;"
                 :: "r"(dst), "l"(src) : "memory");
}
__device__ __forceinline__ void cp_commit() {
    asm volatile("cp.async.commit_group;" ::: "memory");
}
template <int N>
__device__ __forceinline__ void cp_wait() {
    asm volatile("cp.async.wait_group %0;" :: "n"(N) : "memory");
}
__device__ __forceinline__ void ldm_x4(uint32_t& r0, uint32_t& r1,
                                       uint32_t& r2, uint32_t& r3, uint32_t a) {
    asm volatile("ldmatrix.sync.aligned.m8n8.x4.shared.b16 {%0,%1,%2,%3}, [%4];"
                 : "=r"(r0), "=r"(r1), "=r"(r2), "=r"(r3) : "r"(a));
}
__device__ __forceinline__ void mma_f16(float* d, const uint32_t* a,
                                        const uint32_t* b) {
    asm volatile(
        "mma.sync.aligned.m16n8k16.row.col.f32.f16.f16.f32 "
        "{%0,%1,%2,%3}, {%4,%5,%6,%7}, {%8,%9}, {%0,%1,%2,%3};"
        : "+f"(d[0]), "+f"(d[1]), "+f"(d[2]), "+f"(d[3])
        : "r"(a[0]), "r"(a[1]), "r"(a[2]), "r"(a[3]), "r"(b[0]), "r"(b[1]));
}

// ---------------- fp16 mma.sync GEMM (lean epilogues, 1 bar/kt) --------
// EPI=1: Ch = half(max(acc*ESC1,1e-5)*S_REC); rowsum[r] += clipped (fp32)
// EPI=2: Cf = max(Cf_old * acc*ESC2, 1e-5)
// EPI=3: Cf = max((1/F_OUT) * acc*ESC2, 1e-5)
template <int EPI>
__global__ void __launch_bounds__(256, 2)
gemm_f16(const __half* __restrict__ A, const __half* __restrict__ B,
         __half* __restrict__ Ch, float* __restrict__ Cf,
         float* __restrict__ rowsum, int K, int Nglob) {
    extern __shared__ char smem[];
    const uint32_t sb = smem_u32(smem);

    const int tid  = threadIdx.x;
    const int warp = tid >> 5;
    const int lane = tid & 31;
    const int m0 = blockIdx.y * BM;
    const int n0 = blockIdx.x * BN;
    const int wm = (warp >> 1) << 5;
    const int wn = (warp & 1) << 6;

    const int crow = tid >> 3;
    const int cch  = tid & 7;

    const int rowA = wm + (lane & 15);
    const int selA = lane >> 4;
    const int rowB0 = wn + (lane & 7) + ((lane & 16) ? 8 : 0);
    const int selB = (lane >> 3) & 1;

    float acc[2][8][4];
#pragma unroll
    for (int i = 0; i < 2; i++)
#pragma unroll
        for (int j = 0; j < 8; j++)
#pragma unroll
            for (int k = 0; k < 4; k++) acc[i][j][k] = 0.0f;

    const int nkt = K / BK;

    auto load_stage = [&](int kt, int st) {
        const uint32_t sA = sb + st * STAGE_BYTES;
        const uint32_t sB = sA + TILE_BYTES;
        const __half* gA = A + (size_t)m0 * K + kt * BK;
        const __half* gB = B + (size_t)n0 * K + kt * BK;
#pragma unroll
        for (int q = 0; q < 4; q++) {
            const int r = crow + q * 32;
            const uint32_t soff = r * 128 + ((cch ^ (r & 7)) << 4);
            cp_async16(sA + soff, gA + (size_t)r * K + cch * 8);
            cp_async16(sB + soff, gB + (size_t)r * K + cch * 8);
        }
        cp_commit();
    };

    load_stage(0, 0);
    if (nkt > 1) load_stage(1, 1); else cp_commit();

    for (int kt = 0; kt < nkt; kt++) {
        cp_wait<1>();
        // single barrier per kt: also guarantees all threads finished
        // mma(kt-1) before anyone overwrites stage (kt-1)%3 == (kt+2)%3
        __syncthreads();
        if (kt + 2 < nkt) load_stage(kt + 2, (kt + 2) % STAGES);
        else cp_commit();

        const uint32_t sA = sb + (kt % STAGES) * STAGE_BYTES;
        const uint32_t sB = sA + TILE_BYTES;
#pragma unroll
        for (int ks = 0; ks < BK / 16; ks++) {
            uint32_t a[2][4], b[4][4];
#pragma unroll
            for (int mi = 0; mi < 2; mi++) {
                const int r = rowA + mi * 16;
                const uint32_t ad = sA + r * 128 +
                                    (((ks * 2 + selA) ^ (r & 7)) << 4);
                ldm_x4(a[mi][0], a[mi][1], a[mi][2], a[mi][3], ad);
            }
#pragma unroll
            for (int g = 0; g < 4; g++) {
                const int r = rowB0 + g * 16;
                const uint32_t bd = sB + r * 128 +
                                    (((ks * 2 + selB) ^ (r & 7)) << 4);
                ldm_x4(b[g][0], b[g][1], b[g][2], b[g][3], bd);
            }
#pragma unroll
            for (int mi = 0; mi < 2; mi++)
#pragma unroll
                for (int g = 0; g < 4; g++) {
                    mma_f16(acc[mi][2 * g + 0], a[mi], &b[g][0]);
                    mma_f16(acc[mi][2 * g + 1], a[mi], &b[g][2]);
                }
        }
        // no trailing barrier: top-of-loop barrier covers the WAR hazard
    }

    const int erow = m0 + wm + (lane >> 2);
    const int ecol = n0 + wn + (lane & 3) * 2;
#pragma unroll
    for (int mi = 0; mi < 2; mi++) {
#pragma unroll
        for (int hf = 0; hf < 2; hf++) {
            const int r = erow + mi * 16 + hf * 8;
            float rs = 0.0f;
#pragma unroll
            for (int ni = 0; ni < 8; ni++) {
                const int c = ecol + ni * 8;
                float vx = acc[mi][ni][2 * hf + 0];
                float vy = acc[mi][ni][2 * hf + 1];
                if (EPI == 1) {
                    const float ux = fmaxf(vx * ESC1, SECURE_MIN);
                    const float uy = fmaxf(vy * ESC1, SECURE_MIN);
                    rs += ux + uy;
                    *(half2*)(Ch + (size_t)r * Nglob + c) =
                        __floats2half2_rn(ux * S_REC, uy * S_REC);
                } else if (EPI == 2) {
                    float* p = Cf + (size_t)r * Nglob + c;
                    float2 h = *(const float2*)p;
                    float2 v;
                    v.x = fmaxf(h.x * (vx * ESC2), SECURE_MIN);
                    v.y = fmaxf(h.y * (vy * ESC2), SECURE_MIN);
                    *(float2*)p = v;
                } else {
                    float* p = Cf + (size_t)r * Nglob + c;
                    const float h0e = (1.0f / (float)F_OUT) * ESC2;
                    float2 v;
                    v.x = fmaxf(vx * h0e, SECURE_MIN);
                    v.y = fmaxf(vy * h0e, SECURE_MIN);
                    *(float2*)p = v;
                }
            }
            if (EPI == 1) {
                rs += __shfl_xor_sync(0xffffffffu, rs, 1);
                rs += __shfl_xor_sync(0xffffffffu, rs, 2);
                if ((lane & 3) == 0) atomicAdd(&rowsum[r], rs);
            }
        }
    }
}

// ---------------- elementwise ----------------
__device__ __forceinline__ float block_reduce_sum(float v) {
    __shared__ float ws[8];
    const int lane = threadIdx.x & 31;
    const int w    = threadIdx.x >> 5;
#pragma unroll
    for (int o = 16; o > 0; o >>= 1) v += __shfl_xor_sync(0xffffffffu, v, o);
    if (lane == 0) ws[w] = v;
    __syncthreads();
    if (w == 0) {
        v = (lane < 8) ? ws[lane] : 0.0f;
#pragma unroll
        for (int o = 4; o > 0; o >>= 1) v += __shfl_xor_sync(0xffffffffu, v, o);
        if (lane == 0) ws[0] = v;
    }
    __syncthreads();
    return ws[0];
}

__device__ __forceinline__ void store_h4(__half* dst, size_t i4, float4 v,
                                         float scale) {
    half2* p = (half2*)(dst + i4 * 4);
    p[0] = __floats2half2_rn(v.x * scale, v.y * scale);
    p[1] = __floats2half2_rn(v.z * scale, v.w * scale);
}

// fused prep: blocks [0,F_OUT) -> Wn rows (clip+norm, S_W);
// blocks [F_OUT, F_OUT+BATCH) -> xn rows (norm, S_X). blocks<16 zero rec0.
__global__ void __launch_bounds__(256)
rownorm_all_kernel(const float* __restrict__ W, const float* __restrict__ x,
                   __half* __restrict__ Wn_h, __half* __restrict__ xn_h,
                   float* __restrict__ rec0) {
    if (blockIdx.x < 16) rec0[blockIdx.x * 256 + threadIdx.x] = 0.0f;
    const bool isW = blockIdx.x < F_OUT;
    const int row = isW ? blockIdx.x : (blockIdx.x - F_OUT);
    const float* src = isW ? W : x;
    __half* dst = isW ? Wn_h : xn_h;
    const float scale = isW ? S_W : S_X;
    const size_t base = (size_t)row * F_IN;
    const float4* s4 = (const float4*)(src + base);

    float4 v[4];
    float sum = 0.0f;
#pragma unroll
    for (int q = 0; q < 4; q++) {
        v[q] = s4[threadIdx.x + q * 256];
        if (isW) {
            v[q].x = fmaxf(v[q].x, SECURE_MIN); v[q].y = fmaxf(v[q].y, SECURE_MIN);
            v[q].z = fmaxf(v[q].z, SECURE_MIN); v[q].w = fmaxf(v[q].w, SECURE_MIN);
        }
        sum += fabsf(v[q].x) + fabsf(v[q].y) + fabsf(v[q].z) + fabsf(v[q].w);
    }
    const float inv = scale / fmaxf(block_reduce_sum(sum), EPS_NORM);
#pragma unroll
    for (int q = 0; q < 4; q++) {
        float4 u = v[q];
        u.x *= inv; u.y *= inv; u.z *= inv; u.w *= inv;
        store_h4(dst + base, threadIdx.x + q * 256, u, 1.0f);
    }
}

// transpose + fused column-sum (atomics into rec0, units of S_W * true)
__global__ void transpose_h_kernel(const __half* __restrict__ in,
                                   __half* __restrict__ out, int rows, int cols,
                                   float* __restrict__ rec0) {
    __shared__ __half tile[32][33];
    const int c  = blockIdx.x * 32 + threadIdx.x;
    const int r0 = blockIdx.y * 32;
#pragma unroll
    for (int i = threadIdx.y; i < 32; i += 8)
        tile[i][threadIdx.x] = in[(size_t)(r0 + i) * cols + c];
    __syncthreads();
    const int rO = r0 + threadIdx.x;
    const int c0 = blockIdx.x * 32;
#pragma unroll
    for (int i = threadIdx.y; i < 32; i += 8) {
        const __half hv = tile[threadIdx.x][i];
        out[(size_t)(c0 + i) * rows + rO] = hv;
        float s = __half2float(hv);
#pragma unroll
        for (int o = 16; o > 0; o >>= 1)
            s += __shfl_xor_sync(0xffffffffu, s, o);
        if (threadIdx.x == 0) atomicAdd(&rec0[c0 + i], s);
    }
}

// first-iter ratio: computes s0 per-block from rec0 (L2-resident)
__global__ void __launch_bounds__(256)
ratio0_kernel(const float* __restrict__ rec0, const __half* __restrict__ xn_h,
              __half* __restrict__ rat_h) {
    float ps = 0.0f;
    for (int i = threadIdx.x; i < F_IN; i += 256)
        ps += fmaxf(rec0[i] / (S_W * (float)F_OUT), SECURE_MIN);
    const float s0 = fmaxf(block_reduce_sum(ps), EPS_NORM);

    const size_t base = (size_t)blockIdx.x * F_IN;
    const half2* x2 = (const half2*)(xn_h + base);
    half2*       o2 = (half2*)(rat_h + base);
    const float sf = s0 * (S_R / S_X);
    for (int i = threadIdx.x; i < F_IN / 2; i += 256) {
        float2 x = __half22float2(x2[i]);
        const int i2 = i * 2;
        const float ra = fmaxf(rec0[i2]     / (S_W * (float)F_OUT), SECURE_MIN);
        const float rb = fmaxf(rec0[i2 + 1] / (S_W * (float)F_OUT), SECURE_MIN);
        o2[i] = __floats2half2_rn(x.x * sf / ra, x.y * sf / rb);
    }
}

// register-cached h L1 normalize: h -> h (fp32); optionally ht (half S_H);
// thread0 zeroes rowsum[blockIdx.x] for the next GEMM1's atomics.
template <bool WRITE_HT>
__global__ void __launch_bounds__(256)
rownorm_h_kernel(const float* __restrict__ src, float* __restrict__ dst_f,
                 __half* __restrict__ dst_h, float* __restrict__ rowsum) {
    const size_t base = (size_t)blockIdx.x * F_OUT;
    const float4* s4 = (const float4*)(src + base);
    if (WRITE_HT && threadIdx.x == 0) rowsum[blockIdx.x] = 0.0f;

    float4 v[2];
    float sum = 0.0f;
#pragma unroll
    for (int q = 0; q < 2; q++) {
        v[q] = s4[threadIdx.x + q * 256];
        sum += fabsf(v[q].x) + fabsf(v[q].y) + fabsf(v[q].z) + fabsf(v[q].w);
    }
    const float inv = 1.0f / fmaxf(block_reduce_sum(sum), EPS_NORM);
#pragma unroll
    for (int q = 0; q < 2; q++) {
        const int i = threadIdx.x + q * 256;
        float4 u = v[q];
        u.x *= inv; u.y *= inv; u.z *= inv; u.w *= inv;
        ((float4*)(dst_f + base))[i] = u;
        if (WRITE_HT) store_h4(dst_h + base, i, u, S_H);
    }
}

// single-pass ratio using fused rowsum from GEMM1 epilogue
__global__ void __launch_bounds__(256)
ratio_kernel(const __half* __restrict__ rec_h, const __half* __restrict__ xn_h,
             const float* __restrict__ rowsum, __half* __restrict__ rat_h) {
    const size_t base = (size_t)blockIdx.x * F_IN;
    const half2* r2 = (const half2*)(rec_h + base);
    const half2* x2 = (const half2*)(xn_h + base);
    half2*       o2 = (half2*)(rat_h + base);
    const float factor = fmaxf(rowsum[blockIdx.x], EPS_NORM) *
                         (S_R * S_REC / S_X);
    for (int i = threadIdx.x; i < F_IN / 2; i += 256) {
        float2 v = __half22float2(r2[i]);
        float2 x = __half22float2(x2[i]);
        o2[i] = __floats2half2_rn(x.x * factor / v.x, x.y * factor / v.y);
    }
}

// ---------------- host ----------------
extern "C" void kernel_launch(void* const* d_in, const int* in_sizes, int n_in,
                              void* d_out, int out_size) {
    const float* x = (const float*)d_in[0];  // (BATCH, F_IN)
    const float* W = (const float*)d_in[1];  // (F_OUT, F_IN)
    float* h = (float*)d_out;                // (BATCH, F_OUT)

    __half *Wn, *WnT, *rat, *ht, *xn, *rec;
    float *rec0, *rowsum;
    cudaGetSymbolAddress((void**)&Wn,     g_Wn_h);
    cudaGetSymbolAddress((void**)&WnT,    g_WnT_h);
    cudaGetSymbolAddress((void**)&rat,    g_rat_h);
    cudaGetSymbolAddress((void**)&ht,     g_ht_h);
    cudaGetSymbolAddress((void**)&xn,     g_xn_h);
    cudaGetSymbolAddress((void**)&rec,    g_rec_h);
    cudaGetSymbolAddress((void**)&rec0,   g_rec0);
    cudaGetSymbolAddress((void**)&rowsum, g_rowsum);

    cudaFuncSetAttribute(gemm_f16<1>, cudaFuncAttributeMaxDynamicSharedMemorySize, SMEM_TOTAL);
    cudaFuncSetAttribute(gemm_f16<2>, cudaFuncAttributeMaxDynamicSharedMemorySize, SMEM_TOTAL);
    cudaFuncSetAttribute(gemm_f16<3>, cudaFuncAttributeMaxDynamicSharedMemorySize, SMEM_TOTAL);

    const dim3 grid1(F_IN / BN, BATCH / BM);   // GEMM1: N=F_IN, K=F_OUT
    const dim3 grid2(F_OUT / BN, BATCH / BM);  // GEMM2: N=F_OUT, K=F_IN

    // prep: 3 launches (profiled launch #4 = first GEMM)
    rownorm_all_kernel<<<F_OUT + BATCH, 256>>>(W, x, Wn, xn, rec0);
    transpose_h_kernel<<<dim3(F_IN / 32, F_OUT / 32), dim3(32, 8)>>>(
        Wn, WnT, F_OUT, F_IN, rec0);
    ratio0_kernel<<<BATCH, 256>>>(rec0, xn, rat);

    // iteration 1 (h0 uniform => GEMM1 skipped)
    gemm_f16<3><<<grid2, 256, SMEM_TOTAL>>>(rat, Wn, nullptr, h, nullptr,
                                            F_IN, F_OUT);
    rownorm_h_kernel<true><<<BATCH, 256>>>(h, h, ht, rowsum);

    // iterations 2..N
    for (int it = 1; it < N_ITER; ++it) {
        gemm_f16<1><<<grid1, 256, SMEM_TOTAL>>>(ht, WnT, rec, nullptr,
                                                rowsum, F_OUT, F_IN);
        ratio_kernel<<<BATCH, 256>>>(rec, xn, rowsum, rat);
        gemm_f16<2><<<grid2, 256, SMEM_TOTAL>>>(rat, Wn, nullptr, h,
                                                nullptr, F_IN, F_OUT);
        if (it < N_ITER - 1)
            rownorm_h_kernel<true><<<BATCH, 256>>>(h, h, ht, rowsum);
        else
            rownorm_h_kernel<false><<<BATCH, 256>>>(h, h, nullptr, nullptr);
    }
}

// round 13
// speedup vs baseline: 1.0186x; 1.0186x over previous
#include <cuda_runtime.h>
#include <cuda_fp16.h>
#include <math.h>
#include <stdint.h>

#define F_IN   4096
#define F_OUT  2048
#define BATCH  2048
#define N_ITER 10
#define SECURE_MIN 1e-5f
#define EPS_NORM   1e-20f

// static power-of-2 operand scales (exact; cancelled analytically)
#define S_W   65536.0f   // Wn, WnT
#define S_H   4096.0f    // ht
#define S_R   256.0f     // rat' storage scale
#define S_X   4096.0f    // xn half storage
#define ESC1 (1.0f / (S_H * S_W))   // acc1 -> recon_true (pre-clip)
#define ESC2 (1.0f / (S_R * S_W))   // acc2 * rowsum -> update_true
#define C_RAT (S_R / S_X)           // xn_h * C_RAT / u -> rat'_stored

// ---------------- GEMM tiling (proven config) ----------------
#define BM 128
#define BN 128
#define BK 64
#define STAGES 3
#define TILE_BYTES (BM * 128)
#define STAGE_BYTES (2 * TILE_BYTES)
#define SMEM_TOTAL (STAGES * STAGE_BYTES)  // 96 KB -> 2 CTA/SM

// ---------------- scratch ----------------
__device__ __align__(1024) __half g_Wn_h  [(size_t)F_OUT * F_IN];
__device__ __align__(1024) __half g_WnT_h [(size_t)F_IN  * F_OUT];
__device__ __align__(1024) __half g_rat_h [(size_t)BATCH * F_IN];
__device__ __align__(1024) __half g_ht_h  [(size_t)BATCH * F_OUT];
__device__ __align__(1024) __half g_xn_h  [(size_t)BATCH * F_IN];
__device__ float g_rec0[F_IN];      // S_W * colsum(Wn), accumulated by transpose
__device__ float g_rowsum[BATCH];   // per-row sum of clipped recon (true units)

// ---------------- PTX helpers ----------------
__device__ __forceinline__ uint32_t smem_u32(const void* p) {
    uint32_t a;
    asm("{ .reg .u64 t; cvta.to.shared.u64 t, %1; cvt.u32.u64 %0, t; }"
        : "=r"(a) : "l"(p));
    return a;
}
__device__ __forceinline__ void cp_async16(uint32_t dst, const void* src) {
    asm volatile("cp.async.cg.shared.global [%0], [%1], 16;"
                 :: "r"(dst), "l"(src) : "memory");
}
__device__ __forceinline__ void cp_commit() {
    asm volatile("cp.async.commit_group;" ::: "memory");
}
template <int N>
__device__ __forceinline__ void cp_wait() {
    asm volatile("cp.async.wait_group %0;" :: "n"(N) : "memory");
}
__device__ __forceinline__ void ldm_x4(uint32_t& r0, uint32_t& r1,
                                       uint32_t& r2, uint32_t& r3, uint32_t a) {
    asm volatile("ldmatrix.sync.aligned.m8n8.x4.shared.b16 {%0,%1,%2,%3}, [%4];"
                 : "=r"(r0), "=r"(r1), "=r"(r2), "=r"(r3) : "r"(a));
}
__device__ __forceinline__ void mma_f16(float* d, const uint32_t* a,
                                        const uint32_t* b) {
    asm volatile(
        "mma.sync.aligned.m16n8k16.row.col.f32.f16.f16.f32 "
        "{%0,%1,%2,%3}, {%4,%5,%6,%7}, {%8,%9}, {%0,%1,%2,%3};"
        : "+f"(d[0]), "+f"(d[1]), "+f"(d[2]), "+f"(d[3])
        : "r"(a[0]), "r"(a[1]), "r"(a[2]), "r"(a[3]), "r"(b[0]), "r"(b[1]));
}

// ---------------- fp16 mma.sync GEMM ----------------
// EPI=1 (GEMM1): u = max(acc*ESC1, 1e-5); rowsum[r] += u;
//                rat' = half(xn_h * C_RAT / u)   [fuses the ratio kernel]
// EPI=2 (GEMM2): Cf = max(Cf_old * acc * (rowsum[r]*ESC2), 1e-5)
// EPI=3 (first GEMM2): Cf = max((1/F_OUT) * acc*ESC2_0, 1e-5)  [s0 in rat]
template <int EPI>
__global__ void __launch_bounds__(256, 2)
gemm_f16(const __half* __restrict__ A, const __half* __restrict__ B,
         __half* __restrict__ Ch, float* __restrict__ Cf,
         const __half* __restrict__ Xn, float* __restrict__ rowsum,
         int K, int Nglob) {
    extern __shared__ char smem[];
    const uint32_t sb = smem_u32(smem);

    const int tid  = threadIdx.x;
    const int warp = tid >> 5;
    const int lane = tid & 31;
    const int m0 = blockIdx.y * BM;
    const int n0 = blockIdx.x * BN;
    const int wm = (warp >> 1) << 5;
    const int wn = (warp & 1) << 6;

    const int crow = tid >> 3;
    const int cch  = tid & 7;

    const int rowA = wm + (lane & 15);
    const int selA = lane >> 4;
    const int rowB0 = wn + (lane & 7) + ((lane & 16) ? 8 : 0);
    const int selB = (lane >> 3) & 1;

    float acc[2][8][4];
#pragma unroll
    for (int i = 0; i < 2; i++)
#pragma unroll
        for (int j = 0; j < 8; j++)
#pragma unroll
            for (int k = 0; k < 4; k++) acc[i][j][k] = 0.0f;

    const int nkt = K / BK;

    auto load_stage = [&](int kt, int st) {
        const uint32_t sA = sb + st * STAGE_BYTES;
        const uint32_t sB = sA + TILE_BYTES;
        const __half* gA = A + (size_t)m0 * K + kt * BK;
        const __half* gB = B + (size_t)n0 * K + kt * BK;
#pragma unroll
        for (int q = 0; q < 4; q++) {
            const int r = crow + q * 32;
            const uint32_t soff = r * 128 + ((cch ^ (r & 7)) << 4);
            cp_async16(sA + soff, gA + (size_t)r * K + cch * 8);
            cp_async16(sB + soff, gB + (size_t)r * K + cch * 8);
        }
        cp_commit();
    };

    load_stage(0, 0);
    if (nkt > 1) load_stage(1, 1); else cp_commit();

    for (int kt = 0; kt < nkt; kt++) {
        cp_wait<1>();
        __syncthreads();
        if (kt + 2 < nkt) load_stage(kt + 2, (kt + 2) % STAGES);
        else cp_commit();

        const uint32_t sA = sb + (kt % STAGES) * STAGE_BYTES;
        const uint32_t sB = sA + TILE_BYTES;
#pragma unroll
        for (int ks = 0; ks < BK / 16; ks++) {
            uint32_t a[2][4], b[4][4];
#pragma unroll
            for (int mi = 0; mi < 2; mi++) {
                const int r = rowA + mi * 16;
                const uint32_t ad = sA + r * 128 +
                                    (((ks * 2 + selA) ^ (r & 7)) << 4);
                ldm_x4(a[mi][0], a[mi][1], a[mi][2], a[mi][3], ad);
            }
#pragma unroll
            for (int g = 0; g < 4; g++) {
                const int r = rowB0 + g * 16;
                const uint32_t bd = sB + r * 128 +
                                    (((ks * 2 + selB) ^ (r & 7)) << 4);
                ldm_x4(b[g][0], b[g][1], b[g][2], b[g][3], bd);
            }
#pragma unroll
            for (int mi = 0; mi < 2; mi++)
#pragma unroll
                for (int g = 0; g < 4; g++) {
                    mma_f16(acc[mi][2 * g + 0], a[mi], &b[g][0]);
                    mma_f16(acc[mi][2 * g + 1], a[mi], &b[g][2]);
                }
        }
    }

    const int erow = m0 + wm + (lane >> 2);
    const int ecol = n0 + wn + (lane & 3) * 2;
#pragma unroll
    for (int mi = 0; mi < 2; mi++) {
#pragma unroll
        for (int hf = 0; hf < 2; hf++) {
            const int r = erow + mi * 16 + hf * 8;
            float rs = 0.0f;
            float fac;
            if (EPI == 2) fac = rowsum[r] * ESC2;
#pragma unroll
            for (int ni = 0; ni < 8; ni++) {
                const int c = ecol + ni * 8;
                float vx = acc[mi][ni][2 * hf + 0];
                float vy = acc[mi][ni][2 * hf + 1];
                if (EPI == 1) {
                    const float ux = fmaxf(vx * ESC1, SECURE_MIN);
                    const float uy = fmaxf(vy * ESC1, SECURE_MIN);
                    rs += ux + uy;
                    const half2 xv = *(const half2*)(Xn + (size_t)r * Nglob + c);
                    const float2 xf = __half22float2(xv);
                    *(half2*)(Ch + (size_t)r * Nglob + c) =
                        __floats2half2_rn(xf.x * C_RAT / ux,
                                          xf.y * C_RAT / uy);
                } else if (EPI == 2) {
                    float* p = Cf + (size_t)r * Nglob + c;
                    float2 h = *(const float2*)p;
                    float2 v;
                    v.x = fmaxf(h.x * (vx * fac), SECURE_MIN);
                    v.y = fmaxf(h.y * (vy * fac), SECURE_MIN);
                    *(float2*)p = v;
                } else {
                    float* p = Cf + (size_t)r * Nglob + c;
                    const float h0e = (1.0f / (float)F_OUT) * ESC2;
                    float2 v;
                    v.x = fmaxf(vx * h0e, SECURE_MIN);
                    v.y = fmaxf(vy * h0e, SECURE_MIN);
                    *(float2*)p = v;
                }
            }
            if (EPI == 1) {
                rs += __shfl_xor_sync(0xffffffffu, rs, 1);
                rs += __shfl_xor_sync(0xffffffffu, rs, 2);
                if ((lane & 3) == 0) atomicAdd(&rowsum[r], rs);
            }
        }
    }
}

// ---------------- elementwise ----------------
__device__ __forceinline__ float block_reduce_sum(float v) {
    __shared__ float ws[8];
    const int lane = threadIdx.x & 31;
    const int w    = threadIdx.x >> 5;
#pragma unroll
    for (int o = 16; o > 0; o >>= 1) v += __shfl_xor_sync(0xffffffffu, v, o);
    if (lane == 0) ws[w] = v;
    __syncthreads();
    if (w == 0) {
        v = (lane < 8) ? ws[lane] : 0.0f;
#pragma unroll
        for (int o = 4; o > 0; o >>= 1) v += __shfl_xor_sync(0xffffffffu, v, o);
        if (lane == 0) ws[0] = v;
    }
    __syncthreads();
    return ws[0];
}

__device__ __forceinline__ void store_h4(__half* dst, size_t i4, float4 v,
                                         float scale) {
    half2* p = (half2*)(dst + i4 * 4);
    p[0] = __floats2half2_rn(v.x * scale, v.y * scale);
    p[1] = __floats2half2_rn(v.z * scale, v.w * scale);
}

// fused prep: blocks [0,F_OUT) -> Wn rows (clip+norm, S_W);
// blocks [F_OUT, F_OUT+BATCH) -> xn rows (norm, S_X). blocks<16 zero rec0.
__global__ void __launch_bounds__(256)
rownorm_all_kernel(const float* __restrict__ W, const float* __restrict__ x,
                   __half* __restrict__ Wn_h, __half* __restrict__ xn_h,
                   float* __restrict__ rec0) {
    if (blockIdx.x < 16) rec0[blockIdx.x * 256 + threadIdx.x] = 0.0f;
    const bool isW = blockIdx.x < F_OUT;
    const int row = isW ? blockIdx.x : (blockIdx.x - F_OUT);
    const float* src = isW ? W : x;
    __half* dst = isW ? Wn_h : xn_h;
    const float scale = isW ? S_W : S_X;
    const size_t base = (size_t)row * F_IN;
    const float4* s4 = (const float4*)(src + base);

    float4 v[4];
    float sum = 0.0f;
#pragma unroll
    for (int q = 0; q < 4; q++) {
        v[q] = s4[threadIdx.x + q * 256];
        if (isW) {
            v[q].x = fmaxf(v[q].x, SECURE_MIN); v[q].y = fmaxf(v[q].y, SECURE_MIN);
            v[q].z = fmaxf(v[q].z, SECURE_MIN); v[q].w = fmaxf(v[q].w, SECURE_MIN);
        }
        sum += fabsf(v[q].x) + fabsf(v[q].y) + fabsf(v[q].z) + fabsf(v[q].w);
    }
    const float inv = scale / fmaxf(block_reduce_sum(sum), EPS_NORM);
#pragma unroll
    for (int q = 0; q < 4; q++) {
        float4 u = v[q];
        u.x *= inv; u.y *= inv; u.z *= inv; u.w *= inv;
        store_h4(dst + base, threadIdx.x + q * 256, u, 1.0f);
    }
}

// transpose + fused column-sum (atomics into rec0, units of S_W * true)
__global__ void transpose_h_kernel(const __half* __restrict__ in,
                                   __half* __restrict__ out, int rows, int cols,
                                   float* __restrict__ rec0) {
    __shared__ __half tile[32][33];
    const int c  = blockIdx.x * 32 + threadIdx.x;
    const int r0 = blockIdx.y * 32;
#pragma unroll
    for (int i = threadIdx.y; i < 32; i += 8)
        tile[i][threadIdx.x] = in[(size_t)(r0 + i) * cols + c];
    __syncthreads();
    const int rO = r0 + threadIdx.x;
    const int c0 = blockIdx.x * 32;
#pragma unroll
    for (int i = threadIdx.y; i < 32; i += 8) {
        const __half hv = tile[threadIdx.x][i];
        out[(size_t)(c0 + i) * rows + rO] = hv;
        float s = __half2float(hv);
#pragma unroll
        for (int o = 16; o > 0; o >>= 1)
            s += __shfl_xor_sync(0xffffffffu, s, o);
        if (threadIdx.x == 0) atomicAdd(&rec0[c0 + i], s);
    }
}

// first-iter ratio: computes s0 per-block from rec0 (L2-resident),
// rat = half(S_R * xn_true * s0 / rec0_clipped)
__global__ void __launch_bounds__(256)
ratio0_kernel(const float* __restrict__ rec0, const __half* __restrict__ xn_h,
              __half* __restrict__ rat_h) {
    float ps = 0.0f;
    for (int i = threadIdx.x; i < F_IN; i += 256)
        ps += fmaxf(rec0[i] / (S_W * (float)F_OUT), SECURE_MIN);
    const float s0 = fmaxf(block_reduce_sum(ps), EPS_NORM);

    const size_t base = (size_t)blockIdx.x * F_IN;
    const half2* x2 = (const half2*)(xn_h + base);
    half2*       o2 = (half2*)(rat_h + base);
    const float sf = s0 * (S_R / S_X);
    for (int i = threadIdx.x; i < F_IN / 2; i += 256) {
        float2 x = __half22float2(x2[i]);
        const int i2 = i * 2;
        const float ra = fmaxf(rec0[i2]     / (S_W * (float)F_OUT), SECURE_MIN);
        const float rb = fmaxf(rec0[i2 + 1] / (S_W * (float)F_OUT), SECURE_MIN);
        o2[i] = __floats2half2_rn(x.x * sf / ra, x.y * sf / rb);
    }
}

// register-cached h L1 normalize: h -> h (fp32); optionally ht (half S_H);
// thread0 zeroes rowsum[blockIdx.x] for the next GEMM1's atomics.
template <bool WRITE_HT>
__global__ void __launch_bounds__(256)
rownorm_h_kernel(const float* __restrict__ src, float* __restrict__ dst_f,
                 __half* __restrict__ dst_h, float* __restrict__ rowsum) {
    const size_t base = (size_t)blockIdx.x * F_OUT;
    const float4* s4 = (const float4*)(src + base);
    if (WRITE_HT && threadIdx.x == 0) rowsum[blockIdx.x] = 0.0f;

    float4 v[2];
    float sum = 0.0f;
#pragma unroll
    for (int q = 0; q < 2; q++) {
        v[q] = s4[threadIdx.x + q * 256];
        sum += fabsf(v[q].x) + fabsf(v[q].y) + fabsf(v[q].z) + fabsf(v[q].w);
    }
    const float inv = 1.0f / fmaxf(block_reduce_sum(sum), EPS_NORM);
#pragma unroll
    for (int q = 0; q < 2; q++) {
        const int i = threadIdx.x + q * 256;
        float4 u = v[q];
        u.x *= inv; u.y *= inv; u.z *= inv; u.w *= inv;
        ((float4*)(dst_f + base))[i] = u;
        if (WRITE_HT) store_h4(dst_h + base, i, u, S_H);
    }
}

// ---------------- host ----------------
extern "C" void kernel_launch(void* const* d_in, const int* in_sizes, int n_in,
                              void* d_out, int out_size) {
    const float* x = (const float*)d_in[0];  // (BATCH, F_IN)
    const float* W = (const float*)d_in[1];  // (F_OUT, F_IN)
    float* h = (float*)d_out;                // (BATCH, F_OUT)

    __half *Wn, *WnT, *rat, *ht, *xn;
    float *rec0, *rowsum;
    cudaGetSymbolAddress((void**)&Wn,     g_Wn_h);
    cudaGetSymbolAddress((void**)&WnT,    g_WnT_h);
    cudaGetSymbolAddress((void**)&rat,    g_rat_h);
    cudaGetSymbolAddress((void**)&ht,     g_ht_h);
    cudaGetSymbolAddress((void**)&xn,     g_xn_h);
    cudaGetSymbolAddress((void**)&rec0,   g_rec0);
    cudaGetSymbolAddress((void**)&rowsum, g_rowsum);

    cudaFuncSetAttribute(gemm_f16<1>, cudaFuncAttributeMaxDynamicSharedMemorySize, SMEM_TOTAL);
    cudaFuncSetAttribute(gemm_f16<2>, cudaFuncAttributeMaxDynamicSharedMemorySize, SMEM_TOTAL);
    cudaFuncSetAttribute(gemm_f16<3>, cudaFuncAttributeMaxDynamicSharedMemorySize, SMEM_TOTAL);

    const dim3 grid1(F_IN / BN, BATCH / BM);   // GEMM1: N=F_IN, K=F_OUT
    const dim3 grid2(F_OUT / BN, BATCH / BM);  // GEMM2: N=F_OUT, K=F_IN

    // prep: 3 launches (profiled launch #4 = first GEMM)
    rownorm_all_kernel<<<F_OUT + BATCH, 256>>>(W, x, Wn, xn, rec0);
    transpose_h_kernel<<<dim3(F_IN / 32, F_OUT / 32), dim3(32, 8)>>>(
        Wn, WnT, F_OUT, F_IN, rec0);
    ratio0_kernel<<<BATCH, 256>>>(rec0, xn, rat);

    // iteration 1 (h0 uniform => GEMM1 skipped; s0 folded into rat)
    gemm_f16<3><<<grid2, 256, SMEM_TOTAL>>>(rat, Wn, nullptr, h,
                                            nullptr, nullptr, F_IN, F_OUT);
    rownorm_h_kernel<true><<<BATCH, 256>>>(h, h, ht, rowsum);

    // iterations 2..N: GEMM1 writes rat' = xn/u directly (+rowsum),
    // GEMM2 applies the rowsum[r] scalar in its epilogue. No ratio kernel.
    for (int it = 1; it < N_ITER; ++it) {
        gemm_f16<1><<<grid1, 256, SMEM_TOTAL>>>(ht, WnT, rat, nullptr,
                                                xn, rowsum, F_OUT, F_IN);
        gemm_f16<2><<<grid2, 256, SMEM_TOTAL>>>(rat, Wn, nullptr, h,
                                                nullptr, rowsum, F_IN, F_OUT);
        if (it < N_ITER - 1)
            rownorm_h_kernel<true><<<BATCH, 256>>>(h, h, ht, rowsum);
        else
            rownorm_h_kernel<false><<<BATCH, 256>>>(h, h, nullptr, nullptr);
    }
}